// round 14
// baseline (speedup 1.0000x reference)
#include <cuda_runtime.h>

// ProbsToSpan: per batch b,
//   predicted_start[b] = argmax_s ( start[b,s] * suffix_max(end[b,:])[s] )
//   predicted_end[b]   = argmax_t ( end[b,t]   * prefix_max(start[b,:])[t] )
// Exact vs. reference (nonneg probs => monotone fp32 multiply; tie -> first idx).
//
// S=4096, B=16. Grid = 2*B: CTA computes ONE output (role 0 = start, role 1 = end).
// 512 threads (16 warps), 8 elems/thread. Warp-shuffle scan; argmax via
// REDUX + ballot. 2 __syncthreads total. dur_us is at the harness launch
// floor (~6.6us); this is the fastest measured configuration (kernel ~4.2us).

#define S_LEN 4096
#define NT    512
#define NW    16    // warps
#define CHK   8     // elements per thread

#define NEGBIG (-1e30f)
#define FULLM  0xFFFFFFFFu

__global__ __launch_bounds__(NT)
void probs_to_span_kernel(const float* __restrict__ start_p,
                          const float* __restrict__ end_p,
                          float* __restrict__ out, int B) {
    __shared__ float    wT[NW];            // per-warp total max (scanned array)
    __shared__ unsigned aV[NW];            // per-warp best value bits
    __shared__ int      aI[NW];            // per-warp best index

    const int blk  = blockIdx.x;
    const int b    = blk & 15;             // batch
    const int role = blk >> 4;             // 0 = predicted_start, 1 = predicted_end
    const int t    = threadIdx.x;
    const int w    = t >> 5;
    const int lane = t & 31;

    const float4* sp = (const float4*)(start_p + (size_t)b * S_LEN);
    const float4* ep = (const float4*)(end_p   + (size_t)b * S_LEN);

    float4 s0 = sp[2 * t], s1 = sp[2 * t + 1];
    float4 e0 = ep[2 * t], e1 = ep[2 * t + 1];

    float s[CHK] = {s0.x, s0.y, s0.z, s0.w, s1.x, s1.y, s1.z, s1.w};
    float e[CHK] = {e0.x, e0.y, e0.z, e0.w, e1.x, e1.y, e1.z, e1.w};

    float bv = -1.0f;   // all candidates >= 0
    int   bi = 0;

    if (role == 0) {
        // ---- predicted_start: needs suffix-max of END ----
        float emax = fmaxf(fmaxf(fmaxf(e[0], e[4]), fmaxf(e[1], e[5])),
                           fmaxf(fmaxf(e[2], e[6]), fmaxf(e[3], e[7])));
        // Warp inclusive suffix max (by lane).
        float se = emax;
#pragma unroll
        for (int off = 1; off < 32; off <<= 1) {
            float vD = __shfl_down_sync(FULLM, se, off);
            if (lane + off < 32) se = fmaxf(se, vD);
        }
        if (lane == 0) wT[w] = se;         // warp total
        __syncthreads();
        // Cross-warp exclusive tail max (warps after this one), 4-level tree
        // on masked values — reassociated fmax, bit-exact.
        float tv[NW];
#pragma unroll
        for (int i = 0; i < NW; i++) tv[i] = (i > w) ? wT[i] : NEGBIG;
#pragma unroll
        for (int st = 1; st < NW; st <<= 1)
#pragma unroll
            for (int i = 0; i < NW; i += 2 * st)
                tv[i] = fmaxf(tv[i], tv[i + st]);
        float tailE = tv[0];
        // Exclusive within-warp.
        float exE = __shfl_down_sync(FULLM, se, 1);
        if (lane == 31) exE = NEGBIG;
        float runE = fmaxf(tailE, exE);    // max(end) strictly after this chunk
        // Reverse loop; descending j with >= keeps SMALLEST index on ties.
#pragma unroll
        for (int j = CHK - 1; j >= 0; j--) {
            runE = fmaxf(runE, e[j]);
            float f = s[j] * runE;
            if (f >= bv) { bv = f; bi = t * CHK + j; }
        }
    } else {
        // ---- predicted_end: needs prefix-max of START ----
        float smax = fmaxf(fmaxf(fmaxf(s[0], s[4]), fmaxf(s[1], s[5])),
                           fmaxf(fmaxf(s[2], s[6]), fmaxf(s[3], s[7])));
        // Warp inclusive prefix max (by lane).
        float ps = smax;
#pragma unroll
        for (int off = 1; off < 32; off <<= 1) {
            float vU = __shfl_up_sync(FULLM, ps, off);
            if (lane >= off) ps = fmaxf(ps, vU);
        }
        if (lane == 31) wT[w] = ps;        // warp total
        __syncthreads();
        // Cross-warp exclusive head max (warps before this one), 4-level tree.
        float tv[NW];
#pragma unroll
        for (int i = 0; i < NW; i++) tv[i] = (i < w) ? wT[i] : NEGBIG;
#pragma unroll
        for (int st = 1; st < NW; st <<= 1)
#pragma unroll
            for (int i = 0; i < NW; i += 2 * st)
                tv[i] = fmaxf(tv[i], tv[i + st]);
        float headS = tv[0];
        // Exclusive within-warp.
        float exS = __shfl_up_sync(FULLM, ps, 1);
        if (lane == 0) exS = NEGBIG;
        float runS = fmaxf(headS, exS);    // max(start) strictly before this chunk
        // Forward loop; strict > keeps FIRST index on ties.
#pragma unroll
        for (int j = 0; j < CHK; j++) {
            runS = fmaxf(runS, s[j]);
            float g = e[j] * runS;
            if (g > bv) { bv = g; bi = t * CHK + j; }
        }
    }

    // Warp argmax via REDUX on fp32 bits (nonneg => order-monotone);
    // lowest matching lane holds the smallest index (lane order == index order).
    {
        unsigned vb = __float_as_uint(fmaxf(bv, 0.0f));
        unsigned m  = __reduce_max_sync(FULLM, vb);
        unsigned msk = __ballot_sync(FULLM, vb == m);
        int src = __ffs(msk) - 1;
        int idx = __shfl_sync(FULLM, bi, src);
        if (lane == 0) { aV[w] = m; aI[w] = idx; }
    }
    __syncthreads();

    // Warp 0 finishes the 16-entry reduce.
    if (w == 0) {
        unsigned vb = (lane < NW) ? aV[lane] : 0u;
        int idx     = (lane < NW) ? aI[lane] : 0;
        unsigned m   = __reduce_max_sync(FULLM, vb);
        unsigned msk = __ballot_sync(FULLM, vb == m && lane < NW);
        int src = __ffs(msk) - 1;
        int ans = __shfl_sync(FULLM, idx, src);
        if (lane == 0) out[role * B + b] = (float)ans;
    }
}

extern "C" void kernel_launch(void* const* d_in, const int* in_sizes, int n_in,
                              void* d_out, int out_size) {
    const float* start_p = (const float*)d_in[0];
    const float* end_p   = (const float*)d_in[1];
    float* out = (float*)d_out;

    const int B = in_sizes[0] / S_LEN;  // 16
    probs_to_span_kernel<<<2 * B, NT>>>(start_p, end_p, out, B);
}

// round 15
// speedup vs baseline: 1.2660x; 1.2660x over previous
#include <cuda_runtime.h>

// ProbsToSpan: per batch b,
//   predicted_start[b] = argmax_s ( start[b,s] * suffix_max(end[b,:])[s] )
//   predicted_end[b]   = argmax_t ( end[b,t]   * prefix_max(start[b,:])[t] )
// Exact vs. reference (nonneg probs => monotone fp32 multiply; tie -> first idx).
//
// S=4096, B=16. Grid = 2*B: CTA computes ONE output (role 0 = start, role 1 = end),
// halving the post-load critical path. 512 threads (16 warps), 8 elems/thread.
// Warp-shuffle scan; argmax via REDUX + ballot. 2 __syncthreads total.
// R12 measured-best configuration (kernel 4.22us; dur at the ~6.6us harness floor).
// R14's tree-gather variant regressed (LDS pressure) — linear masked loop kept.

#define S_LEN 4096
#define NT    512
#define NW    16    // warps
#define CHK   8     // elements per thread

#define NEGBIG (-1e30f)
#define FULLM  0xFFFFFFFFu

__global__ __launch_bounds__(NT)
void probs_to_span_kernel(const float* __restrict__ start_p,
                          const float* __restrict__ end_p,
                          float* __restrict__ out, int B) {
    __shared__ float    wT[NW];            // per-warp total max (scanned array)
    __shared__ unsigned aV[NW];            // per-warp best value bits
    __shared__ int      aI[NW];            // per-warp best index

    const int blk  = blockIdx.x;
    const int b    = blk & 15;             // batch
    const int role = blk >> 4;             // 0 = predicted_start, 1 = predicted_end
    const int t    = threadIdx.x;
    const int w    = t >> 5;
    const int lane = t & 31;

    const float4* sp = (const float4*)(start_p + (size_t)b * S_LEN);
    const float4* ep = (const float4*)(end_p   + (size_t)b * S_LEN);

    float4 s0 = sp[2 * t], s1 = sp[2 * t + 1];
    float4 e0 = ep[2 * t], e1 = ep[2 * t + 1];

    float s[CHK] = {s0.x, s0.y, s0.z, s0.w, s1.x, s1.y, s1.z, s1.w};
    float e[CHK] = {e0.x, e0.y, e0.z, e0.w, e1.x, e1.y, e1.z, e1.w};

    float bv = -1.0f;   // all candidates >= 0
    int   bi = 0;

    if (role == 0) {
        // ---- predicted_start: needs suffix-max of END ----
        float emax = fmaxf(fmaxf(fmaxf(e[0], e[4]), fmaxf(e[1], e[5])),
                           fmaxf(fmaxf(e[2], e[6]), fmaxf(e[3], e[7])));
        // Warp inclusive suffix max (by lane).
        float se = emax;
#pragma unroll
        for (int off = 1; off < 32; off <<= 1) {
            float vD = __shfl_down_sync(FULLM, se, off);
            if (lane + off < 32) se = fmaxf(se, vD);
        }
        if (lane == 0) wT[w] = se;         // warp total
        __syncthreads();
        // Cross-warp exclusive tail max (warps after this one).
        float tailE = NEGBIG;
#pragma unroll
        for (int i = 0; i < NW; i++)
            if (i > w) tailE = fmaxf(tailE, wT[i]);
        // Exclusive within-warp.
        float exE = __shfl_down_sync(FULLM, se, 1);
        if (lane == 31) exE = NEGBIG;
        float runE = fmaxf(tailE, exE);    // max(end) strictly after this chunk
        // Reverse loop; descending j with >= keeps SMALLEST index on ties.
#pragma unroll
        for (int j = CHK - 1; j >= 0; j--) {
            runE = fmaxf(runE, e[j]);
            float f = s[j] * runE;
            if (f >= bv) { bv = f; bi = t * CHK + j; }
        }
    } else {
        // ---- predicted_end: needs prefix-max of START ----
        float smax = fmaxf(fmaxf(fmaxf(s[0], s[4]), fmaxf(s[1], s[5])),
                           fmaxf(fmaxf(s[2], s[6]), fmaxf(s[3], s[7])));
        // Warp inclusive prefix max (by lane).
        float ps = smax;
#pragma unroll
        for (int off = 1; off < 32; off <<= 1) {
            float vU = __shfl_up_sync(FULLM, ps, off);
            if (lane >= off) ps = fmaxf(ps, vU);
        }
        if (lane == 31) wT[w] = ps;        // warp total
        __syncthreads();
        // Cross-warp exclusive head max (warps before this one).
        float headS = NEGBIG;
#pragma unroll
        for (int i = 0; i < NW; i++)
            if (i < w) headS = fmaxf(headS, wT[i]);
        // Exclusive within-warp.
        float exS = __shfl_up_sync(FULLM, ps, 1);
        if (lane == 0) exS = NEGBIG;
        float runS = fmaxf(headS, exS);    // max(start) strictly before this chunk
        // Forward loop; strict > keeps FIRST index on ties.
#pragma unroll
        for (int j = 0; j < CHK; j++) {
            runS = fmaxf(runS, s[j]);
            float g = e[j] * runS;
            if (g > bv) { bv = g; bi = t * CHK + j; }
        }
    }

    // Warp argmax via REDUX on fp32 bits (nonneg => order-monotone);
    // lowest matching lane holds the smallest index (lane order == index order).
    {
        unsigned vb = __float_as_uint(fmaxf(bv, 0.0f));
        unsigned m  = __reduce_max_sync(FULLM, vb);
        unsigned msk = __ballot_sync(FULLM, vb == m);
        int src = __ffs(msk) - 1;
        int idx = __shfl_sync(FULLM, bi, src);
        if (lane == 0) { aV[w] = m; aI[w] = idx; }
    }
    __syncthreads();

    // Warp 0 finishes the 16-entry reduce.
    if (w == 0) {
        unsigned vb = (lane < NW) ? aV[lane] : 0u;
        int idx     = (lane < NW) ? aI[lane] : 0;
        unsigned m   = __reduce_max_sync(FULLM, vb);
        unsigned msk = __ballot_sync(FULLM, vb == m && lane < NW);
        int src = __ffs(msk) - 1;
        int ans = __shfl_sync(FULLM, idx, src);
        if (lane == 0) out[role * B + b] = (float)ans;
    }
}

extern "C" void kernel_launch(void* const* d_in, const int* in_sizes, int n_in,
                              void* d_out, int out_size) {
    const float* start_p = (const float*)d_in[0];
    const float* end_p   = (const float*)d_in[1];
    float* out = (float*)d_out;

    const int B = in_sizes[0] / S_LEN;  // 16
    probs_to_span_kernel<<<2 * B, NT>>>(start_p, end_p, out, B);
}